// round 1
// baseline (speedup 1.0000x reference)
#include <cuda_runtime.h>

#define BBC 128          // folded batch: B*HEADS*FOLD^3 = 4*4*8
#define NF  4096         // folded spatial 16^3
#define MC  8            // clusters (PROP^3)
#define HD  24           // head dim

// ---------------- scratch (device globals; no allocation) ----------------
__device__ float g_feat[BBC * HD * NF];   // [bb][c][n]
__device__ float g_val [BBC * HD * NF];   // [bb][c][n]
__device__ float g_csum[BBC * MC * HD];   // pooled feat sums
__device__ float g_vsum[BBC * MC * HD];   // pooled value sums
__device__ float g_cn  [BBC * MC * HD];   // normalized centers
__device__ float g_vc  [BBC * MC * HD];   // value centers (means)
__device__ float g_s   [BBC * NF];        // winning sim per point
__device__ int   g_idx [BBC * NF];        // winning cluster per point
__device__ float g_aggD[BBC * MC];        // denominators (sum of s per bin)
__device__ float g_agg [BBC * MC * HD];   // final agg

// ---------------- K1: fused feat+value GEMM (96x96 over 131072 pts) -------
// grid.x = 2048 tiles of 64 consecutive spatial points; block 256 threads.
// smem: xs[96][64], ws[192][100] (feat rows 0..95, value rows 96..191).
__global__ void k1_gemm(const float* __restrict__ x,
                        const float* __restrict__ fw, const float* __restrict__ fb,
                        const float* __restrict__ vw, const float* __restrict__ vb)
{
    extern __shared__ float sm[];
    float* xs = sm;                 // 96*64
    float* ws = sm + 96 * 64;       // 192*100

    const int b   = blockIdx.x >> 9;          // 512 tiles per batch
    const int sp0 = (blockIdx.x & 511) << 6;  // first spatial point
    const int tid = threadIdx.x;

    const float* xb = x + ((size_t)b * 96) * 32768 + sp0;
    for (int i = tid; i < 96 * 64; i += 256)
        xs[i] = xb[(size_t)(i >> 6) * 32768 + (i & 63)];
    for (int i = tid; i < 96 * 96; i += 256) {
        int r = i / 96, cc = i % 96;
        ws[r * 100 + cc]        = fw[i];
        ws[9600 + r * 100 + cc] = vw[i];
    }
    __syncthreads();

    const int pg = tid & 15, cg = tid >> 4;
    const int p0 = pg << 2;
    const int rbase = cg * 6;

    float acc[12][4];
#pragma unroll
    for (int q = 0; q < 12; q++)
#pragma unroll
        for (int k = 0; k < 4; k++) acc[q][k] = 0.f;

    for (int cin = 0; cin < 96; cin += 4) {
        float4 wv[12];
#pragma unroll
        for (int q = 0; q < 12; q++) {
            int row = (q < 6) ? (rbase + q) : (96 + rbase + q - 6);
            wv[q] = *(const float4*)&ws[row * 100 + cin];
        }
#pragma unroll
        for (int k = 0; k < 4; k++) {
            float4 xv = *(const float4*)&xs[(cin + k) * 64 + p0];
#pragma unroll
            for (int q = 0; q < 12; q++) {
                float wk = (k == 0) ? wv[q].x : (k == 1) ? wv[q].y
                         : (k == 2) ? wv[q].z : wv[q].w;
                acc[q][0] += wk * xv.x;
                acc[q][1] += wk * xv.y;
                acc[q][2] += wk * xv.z;
                acc[q][3] += wk * xv.w;
            }
        }
    }

    // epilogue: write into folded layout [bb][c][n]
    const int sp = sp0 + p0;
    const int D = sp & 31, H = (sp >> 5) & 31, W = (sp >> 10) & 31;
    const int f  = ((W >> 4) << 2) | ((H >> 4) << 1) | (D >> 4);
    const int n0 = ((W & 15) << 8) | ((H & 15) << 4) | (D & 15);
#pragma unroll
    for (int q = 0; q < 12; q++) {
        int cout = rbase + ((q < 6) ? q : q - 6);
        int e = cout / 24, c = cout % 24;
        int bb = (b * 4 + e) * 8 + f;
        float bv = (q < 6) ? fb[cout] : vb[cout];
        float* dst = (q < 6) ? g_feat : g_val;
        float4 o;
        o.x = acc[q][0] + bv; o.y = acc[q][1] + bv;
        o.z = acc[q][2] + bv; o.w = acc[q][3] + bv;
        *(float4*)&dst[(((bb * 24) + c) << 12) + n0] = o;
    }
}

// ---------------- K2a: pooled sums per (bb,c) ------------------------------
// grid = 128*24, 128 threads
__global__ void k2a_pool()
{
    const int blk = blockIdx.x;      // bb*24 + c
    const int bb = blk / 24, c = blk % 24;
    const float* fr = g_feat + (size_t)blk * NF;
    const float* vr = g_val  + (size_t)blk * NF;
    const int t = threadIdx.x;

    float fa[8], va[8];
#pragma unroll
    for (int m = 0; m < 8; m++) { fa[m] = 0.f; va[m] = 0.f; }

    for (int j = 0; j < 32; j++) {
        int n = t + (j << 7);
        int m = (((n >> 11) & 1) << 2) | (((n >> 7) & 1) << 1) | ((n >> 3) & 1);
        float fv = fr[n], vv = vr[n];
#pragma unroll
        for (int mm = 0; mm < 8; mm++) {
            fa[mm] += (m == mm) ? fv : 0.f;
            va[mm] += (m == mm) ? vv : 0.f;
        }
    }
#pragma unroll
    for (int mm = 0; mm < 8; mm++)
        for (int o = 16; o; o >>= 1) {
            fa[mm] += __shfl_down_sync(0xFFFFFFFFu, fa[mm], o);
            va[mm] += __shfl_down_sync(0xFFFFFFFFu, va[mm], o);
        }
    __shared__ float sf[8][4], sv[8][4];
    int w = t >> 5, l = t & 31;
    if (l == 0) {
#pragma unroll
        for (int mm = 0; mm < 8; mm++) { sf[mm][w] = fa[mm]; sv[mm][w] = va[mm]; }
    }
    __syncthreads();
    if (t < 8) {
        float s1 = sf[t][0] + sf[t][1] + sf[t][2] + sf[t][3];
        float s2 = sv[t][0] + sv[t][1] + sv[t][2] + sv[t][3];
        g_csum[(bb * 8 + t) * 24 + c] = s1;
        g_vsum[(bb * 8 + t) * 24 + c] = s2;
    }
}

// ---------------- K2b: normalize centers -----------------------------------
// grid = 128*8, 32 threads
__global__ void k2b_norm()
{
    const int bm = blockIdx.x;
    const int t = threadIdx.x;
    float cm = 0.f, vm = 0.f;
    if (t < 24) {
        cm = g_csum[bm * 24 + t] * (1.f / 512.f);
        vm = g_vsum[bm * 24 + t] * (1.f / 512.f);
    }
    float sq = cm * cm;
    for (int o = 16; o; o >>= 1) sq += __shfl_down_sync(0xFFFFFFFFu, sq, o);
    sq = __shfl_sync(0xFFFFFFFFu, sq, 0);
    float nrm = fmaxf(sqrtf(sq), 1e-12f);
    if (t < 24) {
        g_cn[bm * 24 + t] = cm / nrm;
        g_vc[bm * 24 + t] = vm;
    }
}

// ---------------- K3: sim + first-max argmax + denominators ----------------
// grid = 128 (per bb), 512 threads
__global__ void k3_assign(const float* __restrict__ alpha_p,
                          const float* __restrict__ beta_p)
{
    const int bb = blockIdx.x;
    const int t = threadIdx.x;
    __shared__ float cn[8][24];
    __shared__ float accD[8];
    if (t < 192) cn[t / 24][t % 24] = g_cn[bb * 192 + t];
    if (t < 8) accD[t] = 0.f;
    const float alpha = *alpha_p, beta = *beta_p;
    __syncthreads();

    const float* fbase = g_feat + (size_t)bb * 24 * NF;
    for (int k = 0; k < 8; k++) {
        int n = t + (k << 9);
        float fv[24];
        float ns = 0.f;
#pragma unroll
        for (int c = 0; c < 24; c++) {
            float v = fbase[c * NF + n];
            fv[c] = v;
            ns += v * v;
        }
        float inv = 1.f / fmaxf(sqrtf(ns), 1e-12f);
        float best = -3.4e38f;
        int bi = 0;
#pragma unroll
        for (int m = 0; m < 8; m++) {
            float d = 0.f;
#pragma unroll
            for (int c = 0; c < 24; c++) d += cn[m][c] * fv[c];
            float z = beta + alpha * d * inv;   // sigmoid monotone: argmax(z)==argmax(sigmoid)
            if (z > best) { best = z; bi = m; } // strict > = first max, like jnp.argmax
        }
        float s = 1.f / (1.f + expf(-best));
        g_s[bb * NF + n] = s;
        g_idx[bb * NF + n] = bi;
#pragma unroll
        for (int m = 0; m < 8; m++) {
            float v = (bi == m) ? s : 0.f;
            for (int o = 16; o; o >>= 1) v += __shfl_down_sync(0xFFFFFFFFu, v, o);
            if ((t & 31) == 0) atomicAdd(&accD[m], v);
        }
    }
    __syncthreads();
    if (t < 8) g_aggD[bb * 8 + t] = accD[t];
}

// ---------------- K4: aggregate numerators + finalize agg ------------------
// grid = 128*24, 256 threads
__global__ void k4_agg()
{
    const int blk = blockIdx.x;       // bb*24 + c
    const int bb = blk / 24, c = blk % 24;
    const float* vr = g_val + (size_t)blk * NF;
    const float* sr = g_s + bb * NF;
    const int*   ir = g_idx + bb * NF;
    const int t = threadIdx.x;

    float acc[8];
#pragma unroll
    for (int m = 0; m < 8; m++) acc[m] = 0.f;

    for (int k = 0; k < 16; k++) {
        int n = t + (k << 8);
        float sv = sr[n] * vr[n];
        int id = ir[n];
#pragma unroll
        for (int m = 0; m < 8; m++) acc[m] += (id == m) ? sv : 0.f;
    }
#pragma unroll
    for (int m = 0; m < 8; m++)
        for (int o = 16; o; o >>= 1) acc[m] += __shfl_down_sync(0xFFFFFFFFu, acc[m], o);

    __shared__ float red[8][8];
    int w = t >> 5, l = t & 31;
    if (l == 0) {
#pragma unroll
        for (int m = 0; m < 8; m++) red[m][w] = acc[m];
    }
    __syncthreads();
    if (t < 8) {
        float s = 0.f;
#pragma unroll
        for (int j = 0; j < 8; j++) s += red[t][j];
        float d = g_aggD[bb * 8 + t];
        g_agg[(bb * 8 + t) * 24 + c] = (s + g_vc[(bb * 8 + t) * 24 + c]) / (d + 1.f);
    }
}

// ---------------- K5: dispatch + proj GEMM ---------------------------------
// grid = 2048 tiles of 64 pts, 256 threads
// smem: xs[96][64] (inner activations), ws[96][100], ss[4][64], os[4][64]
__global__ void k5_proj(const float* __restrict__ pw, const float* __restrict__ pb,
                        float* __restrict__ out)
{
    extern __shared__ float sm[];
    float* xs = sm;                  // 6144
    float* ws = sm + 96 * 64;        // 9600
    float* ss = ws + 96 * 100;       // 256
    int*   os = (int*)(ss + 256);    // 256

    const int b   = blockIdx.x >> 9;
    const int sp0 = (blockIdx.x & 511) << 6;
    const int tid = threadIdx.x;

    { // stage s/idx per (head e, point)
        int e = tid >> 6, pt = tid & 63;
        int sp = sp0 + pt;
        int D = sp & 31, H = (sp >> 5) & 31, W = (sp >> 10) & 31;
        int f = ((W >> 4) << 2) | ((H >> 4) << 1) | (D >> 4);
        int n = ((W & 15) << 8) | ((H & 15) << 4) | (D & 15);
        int bb = (b * 4 + e) * 8 + f;
        ss[tid] = g_s[bb * NF + n];
        os[tid] = (bb * 8 + g_idx[bb * NF + n]) * 24;
    }
    for (int i = tid; i < 96 * 96; i += 256)
        ws[(i / 96) * 100 + (i % 96)] = pw[i];
    __syncthreads();

    for (int i = tid; i < 96 * 64; i += 256) {
        int ci = i >> 6, pt = i & 63;
        int e = ci / 24, c = ci - e * 24;
        xs[i] = g_agg[os[(e << 6) + pt] + c] * ss[(e << 6) + pt];
    }
    __syncthreads();

    const int pg = tid & 15, cg = tid >> 4;
    const int p0 = pg << 2;
    const int rbase = cg * 6;

    float acc[6][4];
#pragma unroll
    for (int q = 0; q < 6; q++)
#pragma unroll
        for (int k = 0; k < 4; k++) acc[q][k] = 0.f;

    for (int cin = 0; cin < 96; cin += 4) {
        float4 wv[6];
#pragma unroll
        for (int q = 0; q < 6; q++)
            wv[q] = *(const float4*)&ws[(rbase + q) * 100 + cin];
#pragma unroll
        for (int k = 0; k < 4; k++) {
            float4 xv = *(const float4*)&xs[(cin + k) * 64 + p0];
#pragma unroll
            for (int q = 0; q < 6; q++) {
                float wk = (k == 0) ? wv[q].x : (k == 1) ? wv[q].y
                         : (k == 2) ? wv[q].z : wv[q].w;
                acc[q][0] += wk * xv.x;
                acc[q][1] += wk * xv.y;
                acc[q][2] += wk * xv.z;
                acc[q][3] += wk * xv.w;
            }
        }
    }
#pragma unroll
    for (int q = 0; q < 6; q++) {
        int cout = rbase + q;
        float bv = pb[cout];
        float4 o;
        o.x = acc[q][0] + bv; o.y = acc[q][1] + bv;
        o.z = acc[q][2] + bv; o.w = acc[q][3] + bv;
        *(float4*)&out[((size_t)(b * 96 + cout)) * 32768 + sp0 + p0] = o;
    }
}

// ---------------- launch ----------------------------------------------------
extern "C" void kernel_launch(void* const* d_in, const int* in_sizes, int n_in,
                              void* d_out, int out_size)
{
    const float* x  = (const float*)d_in[0];
    const float* fw = (const float*)d_in[1];
    const float* fb = (const float*)d_in[2];
    const float* vw = (const float*)d_in[3];
    const float* vb = (const float*)d_in[4];
    const float* pw = (const float*)d_in[5];
    const float* pb = (const float*)d_in[6];
    const float* sa = (const float*)d_in[7];
    const float* sb = (const float*)d_in[8];
    float* out = (float*)d_out;

    const int smem1 = (96 * 64 + 192 * 100) * 4;              // 101376 B
    const int smem5 = (96 * 64 + 96 * 100) * 4 + 256 * 4 * 2; // 65024 B
    cudaFuncSetAttribute(k1_gemm, cudaFuncAttributeMaxDynamicSharedMemorySize, smem1);
    cudaFuncSetAttribute(k5_proj, cudaFuncAttributeMaxDynamicSharedMemorySize, smem5);

    k1_gemm<<<2048, 256, smem1>>>(x, fw, fb, vw, vb);
    k2a_pool<<<BBC * HD, 128>>>();
    k2b_norm<<<BBC * MC, 32>>>();
    k3_assign<<<BBC, 512>>>(sa, sb);
    k4_agg<<<BBC * HD, 256>>>();
    k5_proj<<<2048, 256, smem5>>>(pw, pb, out);
}

// round 2
// speedup vs baseline: 1.2342x; 1.2342x over previous
#include <cuda_runtime.h>

#define BBC 128          // folded batch: B*HEADS*FOLD^3
#define NF  4096         // folded spatial 16^3
#define MC  8            // clusters (PROP^3)
#define HD  24           // head dim

typedef unsigned long long u64;

__device__ __forceinline__ u64 pack2(float a, float b) {
    u64 r; asm("mov.b64 %0, {%1, %2};" : "=l"(r) : "f"(a), "f"(b)); return r;
}
__device__ __forceinline__ float2 unpack2(u64 v) {
    float2 r; asm("mov.b64 {%0, %1}, %2;" : "=f"(r.x), "=f"(r.y) : "l"(v)); return r;
}
__device__ __forceinline__ void ffma2(u64& d, u64 a, u64 b) {
    asm("fma.rn.f32x2 %0, %1, %2, %0;" : "+l"(d) : "l"(a), "l"(b));
}

// ---------------- scratch ----------------
__device__ float g_feat[BBC * HD * NF];
__device__ float g_val [BBC * HD * NF];
__device__ float g_csum[BBC * MC * HD];
__device__ float g_vsum[BBC * MC * HD];
__device__ float g_cn  [BBC * MC * HD];
__device__ float g_vc  [BBC * MC * HD];
__device__ float g_s   [BBC * NF];
__device__ int   g_idx [BBC * NF];
__device__ float g_aggD[BBC * MC];
__device__ float g_agg [BBC * MC * HD];

// ---------------- K1: fused feat+value GEMM via FFMA2 ----------------------
__global__ void __launch_bounds__(256, 2)
k1_gemm(const float* __restrict__ x,
        const float* __restrict__ fw, const float* __restrict__ fb,
        const float* __restrict__ vw, const float* __restrict__ vb)
{
    extern __shared__ float sm[];
    float* xs = sm;                 // 96*64
    float* ws = sm + 96 * 64;       // 192*100

    const int b   = blockIdx.x >> 9;
    const int sp0 = (blockIdx.x & 511) << 6;
    const int tid = threadIdx.x;

    const float* xb = x + ((size_t)b * 96) * 32768 + sp0;
    for (int i = tid; i < 96 * 64; i += 256)
        xs[i] = xb[(size_t)(i >> 6) * 32768 + (i & 63)];
    for (int i = tid; i < 96 * 96; i += 256) {
        int r = i / 96, cc = i % 96;
        ws[r * 100 + cc]        = fw[i];
        ws[9600 + r * 100 + cc] = vw[i];
    }
    __syncthreads();

    const int pg = tid & 15, cg = tid >> 4;
    const int p0 = pg << 2;
    const int rbase = cg * 6;

    u64 acc[12][2];
#pragma unroll
    for (int q = 0; q < 12; q++) { acc[q][0] = 0ull; acc[q][1] = 0ull; }

    for (int cin = 0; cin < 96; cin += 4) {
        float4 wv[12];
#pragma unroll
        for (int q = 0; q < 12; q++) {
            int row = (q < 6) ? (rbase + q) : (96 + rbase + q - 6);
            wv[q] = *(const float4*)&ws[row * 100 + cin];
        }
#pragma unroll
        for (int k = 0; k < 4; k++) {
            float4 xv = *(const float4*)&xs[(cin + k) * 64 + p0];
            u64 x01 = pack2(xv.x, xv.y);
            u64 x23 = pack2(xv.z, xv.w);
#pragma unroll
            for (int q = 0; q < 12; q++) {
                float wk = (k == 0) ? wv[q].x : (k == 1) ? wv[q].y
                         : (k == 2) ? wv[q].z : wv[q].w;
                u64 ww = pack2(wk, wk);
                ffma2(acc[q][0], x01, ww);
                ffma2(acc[q][1], x23, ww);
            }
        }
    }

    const int sp = sp0 + p0;
    const int D = sp & 31, H = (sp >> 5) & 31, W = (sp >> 10) & 31;
    const int f  = ((W >> 4) << 2) | ((H >> 4) << 1) | (D >> 4);
    const int n0 = ((W & 15) << 8) | ((H & 15) << 4) | (D & 15);
#pragma unroll
    for (int q = 0; q < 12; q++) {
        int cout = rbase + ((q < 6) ? q : q - 6);
        int e = cout / 24, c = cout % 24;
        int bb = (b * 4 + e) * 8 + f;
        float bv = (q < 6) ? fb[cout] : vb[cout];
        float* dst = (q < 6) ? g_feat : g_val;
        float2 a01 = unpack2(acc[q][0]);
        float2 a23 = unpack2(acc[q][1]);
        float4 o;
        o.x = a01.x + bv; o.y = a01.y + bv;
        o.z = a23.x + bv; o.w = a23.y + bv;
        *(float4*)&dst[(((bb * 24) + c) << 12) + n0] = o;
    }
}

// ---------------- K2a: pooled sums (float4 vectorized) ---------------------
// grid = 128*24, 128 threads; 4-aligned float4 shares one m-bin.
__global__ void k2a_pool()
{
    const int blk = blockIdx.x;
    const int bb = blk / 24, c = blk % 24;
    const float4* fr = (const float4*)(g_feat + (size_t)blk * NF);
    const float4* vr = (const float4*)(g_val  + (size_t)blk * NF);
    const int t = threadIdx.x;

    float fa[8], va[8];
#pragma unroll
    for (int m = 0; m < 8; m++) { fa[m] = 0.f; va[m] = 0.f; }

    for (int j = 0; j < 8; j++) {
        int v4 = t + (j << 7);            // float4 index, n = v4*4
        int n = v4 << 2;
        int m = (((n >> 11) & 1) << 2) | (((n >> 7) & 1) << 1) | ((n >> 3) & 1);
        float4 fv = fr[v4], vv = vr[v4];
        float fs = fv.x + fv.y + fv.z + fv.w;
        float vs = vv.x + vv.y + vv.z + vv.w;
#pragma unroll
        for (int mm = 0; mm < 8; mm++) {
            fa[mm] += (m == mm) ? fs : 0.f;
            va[mm] += (m == mm) ? vs : 0.f;
        }
    }
#pragma unroll
    for (int mm = 0; mm < 8; mm++)
        for (int o = 16; o; o >>= 1) {
            fa[mm] += __shfl_down_sync(0xFFFFFFFFu, fa[mm], o);
            va[mm] += __shfl_down_sync(0xFFFFFFFFu, va[mm], o);
        }
    __shared__ float sf[8][4], sv[8][4];
    int w = t >> 5, l = t & 31;
    if (l == 0) {
#pragma unroll
        for (int mm = 0; mm < 8; mm++) { sf[mm][w] = fa[mm]; sv[mm][w] = va[mm]; }
    }
    __syncthreads();
    if (t < 8) {
        g_csum[(bb * 8 + t) * 24 + c] = sf[t][0] + sf[t][1] + sf[t][2] + sf[t][3];
        g_vsum[(bb * 8 + t) * 24 + c] = sv[t][0] + sv[t][1] + sv[t][2] + sv[t][3];
    }
}

// ---------------- K2b: normalize centers + zero denominators ---------------
__global__ void k2b_norm()
{
    const int bm = blockIdx.x;
    const int t = threadIdx.x;
    float cm = 0.f, vm = 0.f;
    if (t < 24) {
        cm = g_csum[bm * 24 + t] * (1.f / 512.f);
        vm = g_vsum[bm * 24 + t] * (1.f / 512.f);
    }
    float sq = cm * cm;
    for (int o = 16; o; o >>= 1) sq += __shfl_down_sync(0xFFFFFFFFu, sq, o);
    sq = __shfl_sync(0xFFFFFFFFu, sq, 0);
    float nrm = fmaxf(sqrtf(sq), 1e-12f);
    if (t < 24) {
        g_cn[bm * 24 + t] = cm / nrm;
        g_vc[bm * 24 + t] = vm;
    }
    if (t == 0) g_aggD[bm] = 0.f;
}

// ---------------- K3: sim + argmax + denominators (512 blocks) -------------
// grid = 512 (bb*4+chunk), 512 threads, 1024 points per block
__global__ void k3_assign(const float* __restrict__ alpha_p,
                          const float* __restrict__ beta_p)
{
    const int blk = blockIdx.x;
    const int bb = blk >> 2, chunk = blk & 3;
    const int t = threadIdx.x;
    __shared__ float cn[8][24];
    __shared__ float accD[8];
    if (t < 192) cn[t / 24][t % 24] = g_cn[bb * 192 + t];
    if (t < 8) accD[t] = 0.f;
    const float alpha = *alpha_p, beta = *beta_p;
    __syncthreads();

    const float* fbase = g_feat + (size_t)bb * 24 * NF + (chunk << 10);
    for (int k = 0; k < 2; k++) {
        int n = t + (k << 9);
        float fv[24];
        float ns = 0.f;
#pragma unroll
        for (int c = 0; c < 24; c++) {
            float v = fbase[c * NF + n];
            fv[c] = v;
            ns += v * v;
        }
        float inv = 1.f / fmaxf(sqrtf(ns), 1e-12f);
        float best = -3.4e38f;
        int bi = 0;
#pragma unroll
        for (int m = 0; m < 8; m++) {
            float d = 0.f;
#pragma unroll
            for (int c = 0; c < 24; c++) d += cn[m][c] * fv[c];
            float z = beta + alpha * d * inv;
            if (z > best) { best = z; bi = m; }   // first max, like jnp.argmax
        }
        float s = 1.f / (1.f + expf(-best));
        g_s[bb * NF + (chunk << 10) + n] = s;
        g_idx[bb * NF + (chunk << 10) + n] = bi;
        atomicAdd(&accD[bi], s);
    }
    __syncthreads();
    if (t < 8) atomicAdd(&g_aggD[bb * 8 + t], accD[t]);
}

// ---------------- K4: aggregate numerators + finalize ----------------------
__global__ void k4_agg()
{
    const int blk = blockIdx.x;
    const int bb = blk / 24, c = blk % 24;
    const float* vr = g_val + (size_t)blk * NF;
    const float* sr = g_s + bb * NF;
    const int*   ir = g_idx + bb * NF;
    const int t = threadIdx.x;

    float acc[8];
#pragma unroll
    for (int m = 0; m < 8; m++) acc[m] = 0.f;

    for (int k = 0; k < 16; k++) {
        int n = t + (k << 8);
        float sv = sr[n] * vr[n];
        int id = ir[n];
#pragma unroll
        for (int m = 0; m < 8; m++) acc[m] += (id == m) ? sv : 0.f;
    }
#pragma unroll
    for (int m = 0; m < 8; m++)
        for (int o = 16; o; o >>= 1) acc[m] += __shfl_down_sync(0xFFFFFFFFu, acc[m], o);

    __shared__ float red[8][8];
    int w = t >> 5, l = t & 31;
    if (l == 0) {
#pragma unroll
        for (int m = 0; m < 8; m++) red[m][w] = acc[m];
    }
    __syncthreads();
    if (t < 8) {
        float s = 0.f;
#pragma unroll
        for (int j = 0; j < 8; j++) s += red[t][j];
        float d = g_aggD[bb * 8 + t];
        g_agg[(bb * 8 + t) * 24 + c] = (s + g_vc[(bb * 8 + t) * 24 + c]) / (d + 1.f);
    }
}

// ---------------- K5: dispatch + proj GEMM via FFMA2 -----------------------
__global__ void __launch_bounds__(256, 2)
k5_proj(const float* __restrict__ pw, const float* __restrict__ pb,
        float* __restrict__ out)
{
    extern __shared__ float sm[];
    float* xs = sm;                  // 6144
    float* ws = sm + 96 * 64;        // 9600
    float* ss = ws + 96 * 100;       // 256
    int*   os = (int*)(ss + 256);    // 256

    const int b   = blockIdx.x >> 9;
    const int sp0 = (blockIdx.x & 511) << 6;
    const int tid = threadIdx.x;

    {
        int e = tid >> 6, pt = tid & 63;
        int sp = sp0 + pt;
        int D = sp & 31, H = (sp >> 5) & 31, W = (sp >> 10) & 31;
        int f = ((W >> 4) << 2) | ((H >> 4) << 1) | (D >> 4);
        int n = ((W & 15) << 8) | ((H & 15) << 4) | (D & 15);
        int bb = (b * 4 + e) * 8 + f;
        ss[tid] = g_s[bb * NF + n];
        os[tid] = (bb * 8 + g_idx[bb * NF + n]) * 24;
    }
    for (int i = tid; i < 96 * 96; i += 256)
        ws[(i / 96) * 100 + (i % 96)] = pw[i];
    __syncthreads();

    for (int i = tid; i < 96 * 64; i += 256) {
        int ci = i >> 6, pt = i & 63;
        int e = ci / 24, c = ci - e * 24;
        xs[i] = g_agg[os[(e << 6) + pt] + c] * ss[(e << 6) + pt];
    }
    __syncthreads();

    const int pg = tid & 15, cg = tid >> 4;
    const int p0 = pg << 2;
    const int rbase = cg * 6;

    u64 acc[6][2];
#pragma unroll
    for (int q = 0; q < 6; q++) { acc[q][0] = 0ull; acc[q][1] = 0ull; }

    for (int cin = 0; cin < 96; cin += 4) {
        float4 wv[6];
#pragma unroll
        for (int q = 0; q < 6; q++)
            wv[q] = *(const float4*)&ws[(rbase + q) * 100 + cin];
#pragma unroll
        for (int k = 0; k < 4; k++) {
            float4 xv = *(const float4*)&xs[(cin + k) * 64 + p0];
            u64 x01 = pack2(xv.x, xv.y);
            u64 x23 = pack2(xv.z, xv.w);
#pragma unroll
            for (int q = 0; q < 6; q++) {
                float wk = (k == 0) ? wv[q].x : (k == 1) ? wv[q].y
                         : (k == 2) ? wv[q].z : wv[q].w;
                u64 ww = pack2(wk, wk);
                ffma2(acc[q][0], x01, ww);
                ffma2(acc[q][1], x23, ww);
            }
        }
    }
#pragma unroll
    for (int q = 0; q < 6; q++) {
        int cout = rbase + q;
        float bv = pb[cout];
        float2 a01 = unpack2(acc[q][0]);
        float2 a23 = unpack2(acc[q][1]);
        float4 o;
        o.x = a01.x + bv; o.y = a01.y + bv;
        o.z = a23.x + bv; o.w = a23.y + bv;
        *(float4*)&out[((size_t)(b * 96 + cout)) * 32768 + sp0 + p0] = o;
    }
}

// ---------------- launch ----------------------------------------------------
extern "C" void kernel_launch(void* const* d_in, const int* in_sizes, int n_in,
                              void* d_out, int out_size)
{
    const float* x  = (const float*)d_in[0];
    const float* fw = (const float*)d_in[1];
    const float* fb = (const float*)d_in[2];
    const float* vw = (const float*)d_in[3];
    const float* vb = (const float*)d_in[4];
    const float* pw = (const float*)d_in[5];
    const float* pb = (const float*)d_in[6];
    const float* sa = (const float*)d_in[7];
    const float* sb = (const float*)d_in[8];
    float* out = (float*)d_out;

    const int smem1 = (96 * 64 + 192 * 100) * 4;
    const int smem5 = (96 * 64 + 96 * 100) * 4 + 256 * 4 * 2;
    cudaFuncSetAttribute(k1_gemm, cudaFuncAttributeMaxDynamicSharedMemorySize, smem1);
    cudaFuncSetAttribute(k5_proj, cudaFuncAttributeMaxDynamicSharedMemorySize, smem5);

    k1_gemm<<<2048, 256, smem1>>>(x, fw, fb, vw, vb);
    k2a_pool<<<BBC * HD, 128>>>();
    k2b_norm<<<BBC * MC, 32>>>();
    k3_assign<<<BBC * 4, 512>>>(sa, sb);
    k4_agg<<<BBC * HD, 256>>>();
    k5_proj<<<2048, 256, smem5>>>(pw, pb, out);
}